// round 1
// baseline (speedup 1.0000x reference)
#include <cuda_runtime.h>

#define T_STEPS 2000
#define NB      1024
#define NMUL    16
#define LENF    15
#define NTH     128   // threads per block (4 warps -> SMSPs 0..3)
#define NBLK    128   // 128*128 = 16384 = NB*NMUL

__global__ void __launch_bounds__(NTH, 1)
hbv_kernel(const float* __restrict__ x,      // (T, B, 3)
           const float* __restrict__ ps,     // (B, 288)
           float* __restrict__ out)          // (T, B)
{
    const int tid = blockIdx.x * NTH + threadIdx.x;   // 0..16383
    const int m   = tid & (NMUL - 1);
    const int b   = tid >> 4;

    const float* pb = ps + b * 288 + m;               // phy param i at pb[i*16]

    // --- physical parameters (parRT, parAC are never used by the model) ---
    const float BETA   = 1.0f   + pb[0*16]  * 5.0f;
    const float FC     = 50.0f  + pb[1*16]  * 950.0f;
    const float K0     = 0.05f  + pb[2*16]  * 0.85f;
    const float K1     = 0.01f  + pb[3*16]  * 0.49f;
    const float K2     = 0.001f + pb[4*16]  * 0.199f;
    const float LP     = 0.2f   + pb[5*16]  * 0.8f;
    const float PERC   =          pb[6*16]  * 10.0f;
    const float UZL    =          pb[7*16]  * 100.0f;
    const float TT     = -2.5f  + pb[8*16]  * 5.0f;
    const float CFMAX  = 0.5f   + pb[9*16]  * 9.5f;
    const float CFR    =          pb[10*16] * 0.1f;
    const float CWH    =          pb[11*16] * 0.2f;
    const float BETAET = 0.3f   + pb[12*16] * 4.7f;
    const float Cpar   =          pb[13*16];

    const float invFC    = 1.0f / FC;
    const float invLPFC  = 1.0f / (LP * FC);
    const float CFRCFMAX = CFR * CFMAX;

    // --- routing weights: gammaln prefactor cancels under normalization ---
    const float rout_a = pb[256] * 2.9f;
    const float rout_b = pb[272] * 6.5f;
    const float aa     = fmaxf(rout_a, 0.0f) + 0.1f;
    const float theta  = fmaxf(rout_b, 0.0f) + 0.5f;
    const float itheta = 1.0f / theta;

    float w[LENF];
    float wsum = 0.0f;
#pragma unroll
    for (int k = 0; k < LENF; ++k) {
        const float tk = (float)k + 0.5f;
        w[k] = expf((aa - 1.0f) * logf(tk) - tk * itheta);
        wsum += w[k];
    }
    const float iws = 1.0f / wsum;
#pragma unroll
    for (int k = 0; k < LENF; ++k) w[k] *= iws;

    // --- state ---
    float SP  = 1e-5f;   // SNOWPACK
    float MW  = 1e-5f;   // MELTWATER
    float SMv = 1e-5f;   // SM
    float SUZ = 1e-5f;
    float SLZ = 1e-5f;

    float q[LENF];       // ring of last Qsim values (q[0] = newest)
#pragma unroll
    for (int k = 0; k < LENF; ++k) q[k] = 0.0f;

    const float* xr = x + b * 3;            // row for this grid cell
    float* ob = out + b;
    const float scale = 1.0f / (float)NMUL;

    // double-buffered forcing
    float Pm = xr[0], Tc = xr[1], PE = xr[2];

#pragma unroll 5
    for (int t = 0; t < T_STEPS; ++t) {
        // prefetch next step's forcing (clamped index; off critical path)
        const int tn = (t + 1 < T_STEPS) ? (t + 1) : (T_STEPS - 1);
        const float* xn = xr + tn * (NB * 3);
        const float Pn = xn[0], Tn = xn[1], En = xn[2];

        // --- snow routine ---
        const float rain = (Tc >= TT) ? Pm : 0.0f;
        const float snow = Pm - rain;
        SP += snow;
        const float melt = fminf(fmaxf(CFMAX * (Tc - TT), 0.0f), SP);
        MW += melt; SP -= melt;
        const float refreeze = fminf(fmaxf(CFRCFMAX * (TT - Tc), 0.0f), MW);
        SP += refreeze; MW -= refreeze;
        const float tosoil = fmaxf(MW - CWH * SP, 0.0f);
        MW -= tosoil;

        // --- soil routine ---
        float sw = __powf(SMv * invFC, BETA);
        sw = fminf(fmaxf(sw, 0.0f), 1.0f);
        const float recharge = (rain + tosoil) * sw;
        SMv += rain + tosoil - recharge;
        const float excess = fmaxf(SMv - FC, 0.0f);
        SMv -= excess;
        const float cap = fminf(SLZ, Cpar * SLZ * (1.0f - fminf(SMv * invFC, 1.0f)));
        SMv += cap; SLZ -= cap;
        const float ef = __powf(fminf(fmaxf(SMv * invLPFC, 0.0f), 1.0f), BETAET);
        const float ET = fminf(PE * ef, SMv);
        SMv = fmaxf(SMv - ET, 1e-5f);

        // --- response routine ---
        SUZ += recharge + excess;
        const float PERCv = fminf(SUZ, PERC);
        SUZ -= PERCv;
        const float Q0 = K0 * fmaxf(SUZ - UZL, 0.0f);
        SUZ -= Q0;
        const float Q1 = K1 * SUZ;
        SUZ -= Q1;
        SLZ += PERCv;
        const float Q2 = K2 * SLZ;
        SLZ -= Q2;
        const float Qs = Q0 + Q1 + Q2;

        // --- routing convolution (register ring, off the state chain) ---
#pragma unroll
        for (int k = LENF - 1; k >= 1; --k) q[k] = q[k - 1];
        q[0] = Qs;
        float Qr = 0.0f;
#pragma unroll
        for (int k = 0; k < LENF; ++k) Qr = fmaf(w[k], q[k], Qr);

        // --- reduce over the 16 NMUL lanes (half-warp) & store mean ---
        Qr += __shfl_xor_sync(0xffffffffu, Qr, 1);
        Qr += __shfl_xor_sync(0xffffffffu, Qr, 2);
        Qr += __shfl_xor_sync(0xffffffffu, Qr, 4);
        Qr += __shfl_xor_sync(0xffffffffu, Qr, 8);
        if (m == 0) ob[t * NB] = Qr * scale;

        Pm = Pn; Tc = Tn; PE = En;
    }
}

extern "C" void kernel_launch(void* const* d_in, const int* in_sizes, int n_in,
                              void* d_out, int out_size)
{
    // identify inputs by element count (x_phy: 2000*1024*3, params: 1024*288)
    const float* x  = (const float*)d_in[0];
    const float* ps = (const float*)d_in[1];
    if (n_in >= 2 && in_sizes[0] == NB * 288) {  // swapped order
        x  = (const float*)d_in[1];
        ps = (const float*)d_in[0];
    }
    float* out = (float*)d_out;
    hbv_kernel<<<NBLK, NTH>>>(x, ps, out);
}

// round 2
// speedup vs baseline: 1.3212x; 1.3212x over previous
#include <cuda_runtime.h>

#define T_STEPS 2000
#define NB      1024
#define NMUL    16
#define NTH     128   // 4 warps -> SMSPs 0..3
#define NBLK    128   // 128*128 = 16384 threads = NB*NMUL
#define CH      16    // steps per chunk (= ring size = unroll)
#define NCHUNK  (T_STEPS / CH)   // 125, exact

__global__ void __launch_bounds__(NTH, 1)
hbv_kernel(const float* __restrict__ x,      // (T, B, 3)
           const float* __restrict__ ps,     // (B, 288)
           float* __restrict__ out)          // (T, B)
{
    // per-warp transpose buffer: [warp][cell][m][t] padded to 17 -> conflict-free
    __shared__ float red[4][2][16][17];

    const int tid  = blockIdx.x * NTH + threadIdx.x;   // 0..16383
    const int m    = tid & (NMUL - 1);
    const int b    = tid >> 4;
    const int w_id = threadIdx.x >> 5;
    const int lane = threadIdx.x & 31;
    const int cell = lane >> 4;
    const int tt   = lane & 15;
    // warp covers cells b_base, b_base+1; this lane stores row b_store, time tt
    const int b_store = ((blockIdx.x * NTH + (w_id << 5)) >> 4) + cell;

    const float* pb = ps + b * 288 + m;

    // --- physical parameters (parRT, parAC unused by the model) ---
    const float BETA   = 1.0f   + pb[0*16]  * 5.0f;
    const float FC     = 50.0f  + pb[1*16]  * 950.0f;
    const float K0     = 0.05f  + pb[2*16]  * 0.85f;
    const float K1     = 0.01f  + pb[3*16]  * 0.49f;
    const float K2     = 0.001f + pb[4*16]  * 0.199f;
    const float LP     = 0.2f   + pb[5*16]  * 0.8f;
    const float PERC   =          pb[6*16]  * 10.0f;
    const float UZL    =          pb[7*16]  * 100.0f;
    const float TT     = -2.5f  + pb[8*16]  * 5.0f;
    const float CFMAX  = 0.5f   + pb[9*16]  * 9.5f;
    const float CFR    =          pb[10*16] * 0.1f;
    const float CWH    =          pb[11*16] * 0.2f;
    const float BETAET = 0.3f   + pb[12*16] * 4.7f;
    const float Cpar   =          pb[13*16];

    const float invFC    = 1.0f / FC;
    const float rLP      = 1.0f / LP;
    const float epsF     = 1e-5f * invFC;
    const float CFRCFMAX = CFR * CFMAX;

    // --- routing weights (gammaln prefactor cancels under normalization) ---
    const float aa     = fmaxf(pb[256] * 2.9f, 0.0f) + 0.1f;
    const float theta  = fmaxf(pb[272] * 6.5f, 0.0f) + 0.5f;
    const float itheta = 1.0f / theta;

    float w[CH];
    float wsum = 0.0f;
#pragma unroll
    for (int k = 0; k < 15; ++k) {
        const float tk = (float)k + 0.5f;
        w[k] = expf((aa - 1.0f) * logf(tk) - tk * itheta);
        wsum += w[k];
    }
    const float iws = 1.0f / wsum;
#pragma unroll
    for (int k = 0; k < 15; ++k) w[k] *= iws;
    w[15] = 0.0f;                         // dummy tap so ring period == unroll

    // --- state (y = SM/FC normalized) ---
    float SP  = 1e-5f, MW = 1e-5f, SUZ = 1e-5f, SLZ = 1e-5f;
    float y   = epsF;

    float q[CH];
#pragma unroll
    for (int k = 0; k < CH; ++k) q[k] = 0.0f;

    const float* xr = x + b * 3;
    float Pm = xr[0], Tc = xr[1], PE = xr[2];

#pragma unroll 1
    for (int c = 0; c < NCHUNK; ++c) {
#pragma unroll
        for (int j = 0; j < CH; ++j) {
            const int t = c * CH + j;
            // prefetch next step's forcing (clamped; off critical path)
            const int tn = (t + 1 < T_STEPS) ? (t + 1) : (T_STEPS - 1);
            const float* xn = xr + tn * (NB * 3);
            const float Pn = xn[0], Tn = xn[1], En = xn[2];

            // --- snow routine ---
            const float rain = (Tc >= TT) ? Pm : 0.0f;
            const float snow = Pm - rain;
            const float m0 = fmaxf(CFMAX * (Tc - TT), 0.0f);       // off-chain
            const float r0 = fmaxf(CFRCFMAX * (TT - Tc), 0.0f);    // off-chain
            SP += snow;
            const float melt = fminf(m0, SP);
            MW += melt;  SP -= melt;
            const float refreeze = fminf(r0, MW);
            SP += refreeze;  MW -= refreeze;
            const float tosoil = fmaxf(fmaf(-CWH, SP, MW), 0.0f);
            MW -= tosoil;

            // --- soil routine (y = SM/FC) ---
            const float sw  = fminf(__powf(y, BETA), 1.0f);        // ex2>=0: no low clamp
            const float inr = rain + tosoil;
            const float recharge = inr * sw;
            y = fmaf(inr * invFC, 1.0f - sw, y);
            const float excess = fmaxf(y - 1.0f, 0.0f) * FC;       // feeds SUZ, off y-chain
            y = fminf(y, 1.0f);                                    // == SM -= excess
            // capillary: cap = SLZ*min(1, C*(1-y));  y<=1 here so min(SM/FC,1)==y
            const float u    = fminf(fmaf(-Cpar, y, Cpar), 1.0f);
            const float SLZF = SLZ * invFC;                        // off-chain
            y = fmaf(SLZF, u, y);
            const float cap = SLZ * u;
            SLZ -= cap;
            const float ef  = __powf(fminf(y * rLP, 1.0f), BETAET);
            const float PEF = PE * invFC;                          // off-chain
            y = fmaxf(fmaf(-PEF, ef, y), epsF);                    // fused ET + floor

            // --- response routine ---
            SUZ += recharge + excess;
            const float PERCv = fminf(SUZ, PERC);
            SUZ -= PERCv;
            const float Q0 = K0 * fmaxf(SUZ - UZL, 0.0f);
            SUZ -= Q0;
            const float Q1 = K1 * SUZ;
            SUZ -= Q1;
            SLZ += PERCv;
            const float Q2 = K2 * SLZ;
            SLZ -= Q2;
            const float Qs = Q0 + Q1 + Q2;

            // --- routing conv: ring of 16 (renamed via unroll), 4 accumulators ---
            q[j] = Qs;
            float a0 = 0.f, a1 = 0.f, a2 = 0.f, a3 = 0.f;
#pragma unroll
            for (int k = 0; k < CH; k += 4) {
                a0 = fmaf(w[k + 0], q[(j - k - 0) & 15], a0);
                a1 = fmaf(w[k + 1], q[(j - k - 1) & 15], a1);
                a2 = fmaf(w[k + 2], q[(j - k - 2) & 15], a2);
                a3 = fmaf(w[k + 3], q[(j - k - 3) & 15], a3);
            }
            const float Qr = (a0 + a1) + (a2 + a3);

            // STS: issue-only, no result latency, conflict-free (pad 17)
            red[w_id][cell][m][j] = Qr;

            Pm = Pn; Tc = Tn; PE = En;
        }

        // --- per-16-step transpose reduce over m (replaces 4 serial SHFLs/step) ---
        __syncwarp();
        {
            float s0 = 0.f, s1 = 0.f;
#pragma unroll
            for (int mi = 0; mi < 16; mi += 2) {
                s0 += red[w_id][cell][mi + 0][tt];
                s1 += red[w_id][cell][mi + 1][tt];
            }
            out[(c * CH + tt) * NB + b_store] = (s0 + s1) * 0.0625f;
        }
        __syncwarp();
    }
}

extern "C" void kernel_launch(void* const* d_in, const int* in_sizes, int n_in,
                              void* d_out, int out_size)
{
    const float* x  = (const float*)d_in[0];
    const float* ps = (const float*)d_in[1];
    if (n_in >= 2 && in_sizes[0] == NB * 288) {  // swapped order
        x  = (const float*)d_in[1];
        ps = (const float*)d_in[0];
    }
    float* out = (float*)d_out;
    hbv_kernel<<<NBLK, NTH>>>(x, ps, out);
}